// round 13
// baseline (speedup 1.0000x reference)
#include <cuda_runtime.h>
#include <cuda_bf16.h>
#include <math.h>
#include <stdint.h>

#define Nn 128
#define Tt 256
#define Dd 1024
#define Hh 1024
#define G4 4096
#define Pp 196
#define KR 2048   // recurrent K: [h | attn]
#define MX (Nn * Tt)

// ================= device scratch (static) =================
__device__ __align__(16) __nv_bfloat16 g_Wxh[(size_t)G4 * Dd];
__device__ __align__(16) __nv_bfloat16 g_Wxl[(size_t)G4 * Dd];
__device__ __align__(16) __nv_bfloat16 g_Wfh[(size_t)G4 * KR];
__device__ __align__(16) __nv_bfloat16 g_Wfl[(size_t)G4 * KR];
__device__ __align__(16) __nv_bfloat16 g_xh[(size_t)MX * Dd];
__device__ __align__(16) __nv_bfloat16 g_xl[(size_t)MX * Dd];
__device__ float g_xp[(size_t)MX * G4];
__device__ __align__(16) __nv_bfloat16 g_Atbf[(size_t)Nn * Pp * Hh];  // bf16 A transposed [n][p][u]
__device__ __align__(16) __nv_bfloat16 g_acth[(size_t)Nn * KR];
__device__ __align__(16) __nv_bfloat16 g_actl[(size_t)Nn * KR];
__device__ float g_bf[G4];
__device__ float g_hnewT[Hh * Nn];
__device__ float g_cT[Hh * Nn];
__device__ float g_sp[Nn][8][Pp];

// ================= helpers =================
__device__ __forceinline__ uint32_t smem_u32(const void* p) {
    uint32_t a;
    asm("{ .reg .u64 t; cvta.to.shared.u64 t, %1; cvt.u32.u64 %0, t; }" : "=r"(a) : "l"(p));
    return a;
}
__device__ __forceinline__ void cp16(uint32_t dst, const void* src) {
    asm volatile("cp.async.cg.shared.global [%0], [%1], 16;" :: "r"(dst), "l"(src));
}
__device__ __forceinline__ void cpcommit() { asm volatile("cp.async.commit_group;" ::: "memory"); }
template <int N> __device__ __forceinline__ void cpwait() {
    asm volatile("cp.async.wait_group %0;" :: "n"(N) : "memory");
}
__device__ __forceinline__ void ldsm_x4(uint32_t& r0, uint32_t& r1, uint32_t& r2, uint32_t& r3,
                                        uint32_t addr) {
    asm volatile("ldmatrix.sync.aligned.m8n8.x4.shared.b16 {%0,%1,%2,%3}, [%4];"
                 : "=r"(r0), "=r"(r1), "=r"(r2), "=r"(r3) : "r"(addr));
}
__device__ __forceinline__ void mma16816(float* d, const uint32_t* a, const uint32_t* b) {
    asm volatile(
        "mma.sync.aligned.m16n8k16.row.col.f32.bf16.bf16.f32 "
        "{%0,%1,%2,%3}, {%4,%5,%6,%7}, {%8,%9}, {%0,%1,%2,%3};"
        : "+f"(d[0]), "+f"(d[1]), "+f"(d[2]), "+f"(d[3])
        : "r"(a[0]), "r"(a[1]), "r"(a[2]), "r"(a[3]), "r"(b[0]), "r"(b[1]));
}
#define SWZ128(o) ((o) ^ (((o) >> 3) & 0x70))

__device__ __forceinline__ void bf16split(float v, __nv_bfloat16* hi, __nv_bfloat16* lo) {
    __nv_bfloat16 h = __float2bfloat16(v);
    *hi = h;
    *lo = __float2bfloat16(v - __bfloat162float(h));
}

// ================= one-time kernels =================
__global__ __launch_bounds__(256) void permute_kernel(
    const float* __restrict__ Wx, const float* __restrict__ Wh,
    const float* __restrict__ Wa, const float* __restrict__ b) {
    size_t total = (size_t)G4 * 3072;
    size_t stride = (size_t)gridDim.x * blockDim.x;
    for (size_t idx = (size_t)blockIdx.x * blockDim.x + threadIdx.x; idx < total; idx += stride) {
        int j = (int)(idx / 3072);
        int k = (int)(idx - (size_t)j * 3072);
        int src = (j & 3) * 1024 + (j >> 2);
        __nv_bfloat16 hi, lo;
        if (k < 1024) {
            bf16split(Wx[(size_t)k * G4 + src], &hi, &lo);
            g_Wxh[(size_t)j * Dd + k] = hi;
            g_Wxl[(size_t)j * Dd + k] = lo;
        } else {
            float v = (k < 2048) ? Wh[(size_t)(k - 1024) * G4 + src]
                                 : Wa[(size_t)(k - 2048) * G4 + src];
            bf16split(v, &hi, &lo);
            g_Wfh[(size_t)j * KR + (k - 1024)] = hi;
            g_Wfl[(size_t)j * KR + (k - 1024)] = lo;
        }
        if (k == 0) g_bf[j] = b[src];
    }
}

__global__ __launch_bounds__(256) void xsplit_kernel(const float* __restrict__ x) {
    size_t total = (size_t)MX * Dd;
    size_t stride = (size_t)gridDim.x * blockDim.x;
    for (size_t i = (size_t)blockIdx.x * blockDim.x + threadIdx.x; i < total; i += stride) {
        __nv_bfloat16 hi, lo;
        bf16split(x[i], &hi, &lo);
        g_xh[i] = hi;
        g_xl[i] = lo;
    }
}

// one-time: A[n][u][p] fp32 -> Atbf[n][p][u] bf16 (tile transpose)
__global__ __launch_bounds__(256) void a2bft_kernel(const float* __restrict__ A) {
    __shared__ float tile[32][197];
    int n = blockIdx.y;
    int u0 = blockIdx.x * 32;
    const float* src = A + ((size_t)n * Hh + u0) * Pp;
    for (int i = threadIdx.x; i < 32 * Pp; i += 256) {
        int u = i / Pp, p = i - u * Pp;
        tile[u][p] = src[(size_t)u * Pp + p];
    }
    __syncthreads();
    __nv_bfloat16* dst = g_Atbf + (size_t)n * Pp * Hh + u0;
    for (int i = threadIdx.x; i < 32 * Pp; i += 256) {
        int u = i & 31, p = i >> 5;
        dst[(size_t)p * Hh + u] = __float2bfloat16(tile[u][p]);
    }
}

__global__ __launch_bounds__(256) void init_kernel(const float* __restrict__ A) {
    int n = blockIdx.x;
    for (int u = threadIdx.x; u < Hh; u += blockDim.x) {
        const float4* r = (const float4*)(A + ((size_t)n * Hh + u) * Pp);
        float s = 0.f;
#pragma unroll
        for (int i = 0; i < 49; i++) {
            float4 v = r[i];
            s += v.x + v.y + v.z + v.w;
        }
        float m = s * (1.f / 196.f);
        g_hnewT[u * Nn + n] = m;
        g_cT[u * Nn + n] = m;
    }
}

// ================= generic split-bf16x3 mma mainloop (KC=64, SW128) =================
#define KC 64
#define STB 40960
#define NSTG 3

__device__ __forceinline__ void load_chunk_g(
    int tid, int c, char* buf,
    const __nv_bfloat16* Ah, const __nv_bfloat16* Al, int lda,
    const __nv_bfloat16* Bh, const __nv_bfloat16* Bl, int ldb) {
    uint32_t sbase = smem_u32(buf);
#pragma unroll
    for (int it = 0; it < 4; it++) {
        int id = tid + it * 256;           // 0..1023 : 128 rows x 8 16B-chunks
        int m = id >> 3, kc = id & 7;
        uint32_t off = SWZ128((uint32_t)m * 128 + (uint32_t)kc * 16);
        size_t gidx = (size_t)m * lda + (size_t)c * KC + kc * 8;
        cp16(sbase + off, Ah + gidx);
        cp16(sbase + 16384 + off, Al + gidx);
    }
    {
        int nrow = tid >> 3, kc = tid & 7;  // 256 = 32 rows x 8 chunks
        uint32_t off = SWZ128((uint32_t)nrow * 128 + (uint32_t)kc * 16);
        size_t gidx = (size_t)nrow * ldb + (size_t)c * KC + kc * 8;
        cp16(sbase + 32768 + off, Bh + gidx);
        cp16(sbase + 36864 + off, Bl + gidx);
    }
    cpcommit();
}

__device__ __forceinline__ void mma_mainloop(
    int tid, char* dsm, float acc[4][4], int nch,
    const __nv_bfloat16* Ah, const __nv_bfloat16* Al, int lda,
    const __nv_bfloat16* Bh, const __nv_bfloat16* Bl, int ldb) {
    int w = tid >> 5, lane = tid & 31;
    load_chunk_g(tid, 0, dsm, Ah, Al, lda, Bh, Bl, ldb);
    load_chunk_g(tid, 1, dsm + STB, Ah, Al, lda, Bh, Bl, ldb);
    for (int c = 0; c < nch; c++) {
        if (c + 1 < nch) cpwait<1>(); else cpwait<0>();
        __syncthreads();
        uint32_t sbase = smem_u32(dsm + (c % NSTG) * STB);
        int arow = w * 16 + (lane & 15);
#pragma unroll
        for (int ks = 0; ks < 4; ks++) {
            int ak = ks * 16 + ((lane & 16) ? 8 : 0);
            uint32_t aoff = SWZ128((uint32_t)arow * 128 + (uint32_t)ak * 2);
            uint32_t ah[4], al[4];
            ldsm_x4(ah[0], ah[1], ah[2], ah[3], sbase + aoff);
            ldsm_x4(al[0], al[1], al[2], al[3], sbase + 16384 + aoff);
            uint32_t bh[8], bl[8];
            int bk = ks * 16 + ((lane & 8) ? 8 : 0);
#pragma unroll
            for (int jj = 0; jj < 2; jj++) {
                int nrow = jj * 16 + ((lane & 16) ? 8 : 0) + (lane & 7);
                uint32_t boff = SWZ128((uint32_t)nrow * 128 + (uint32_t)bk * 2);
                ldsm_x4(bh[4 * jj], bh[4 * jj + 1], bh[4 * jj + 2], bh[4 * jj + 3],
                        sbase + 32768 + boff);
                ldsm_x4(bl[4 * jj], bl[4 * jj + 1], bl[4 * jj + 2], bl[4 * jj + 3],
                        sbase + 36864 + boff);
            }
#pragma unroll
            for (int j = 0; j < 4; j++) {
                mma16816(acc[j], ah, &bh[2 * j]);
                mma16816(acc[j], ah, &bl[2 * j]);
                mma16816(acc[j], al, &bh[2 * j]);
            }
        }
        if (c + 2 < nch)
            load_chunk_g(tid, c + 2, dsm + ((c + 2) % NSTG) * STB, Ah, Al, lda, Bh, Bl, ldb);
    }
}

// ================= one-time: xproj = x @ Wx + b =================
__global__ __launch_bounds__(256) void xproj_kernel() {
    extern __shared__ __align__(1024) char dsm[];
    int tid = threadIdx.x;
    int w = tid >> 5, lane = tid & 31;
    int j0 = blockIdx.x * 32;
    int m0 = blockIdx.y * 128;

    float acc[4][4];
#pragma unroll
    for (int j = 0; j < 4; j++)
#pragma unroll
        for (int r = 0; r < 4; r++) acc[j][r] = 0.f;

    mma_mainloop(tid, dsm, acc, Dd / KC,
                 g_xh + (size_t)m0 * Dd, g_xl + (size_t)m0 * Dd, Dd,
                 g_Wxh + (size_t)j0 * Dd, g_Wxl + (size_t)j0 * Dd, Dd);

    int row0 = m0 + w * 16 + (lane >> 2);
#pragma unroll
    for (int j = 0; j < 4; j++) {
        int col = j0 + j * 8 + (lane & 3) * 2;
        float2 bb = *(const float2*)&g_bf[col];
        *(float2*)&g_xp[(size_t)row0 * G4 + col] = make_float2(acc[j][0] + bb.x, acc[j][1] + bb.y);
        *(float2*)&g_xp[(size_t)(row0 + 8) * G4 + col] = make_float2(acc[j][2] + bb.x, acc[j][3] + bb.y);
    }
}

// ================= scores partial: grid (8,128); transposed bf16 A =================
__global__ __launch_bounds__(256) void scores_kernel(int t) {
    int uc = blockIdx.x;
    int n = (t & 1) ? (Nn - 1 - (int)blockIdx.y) : (int)blockIdx.y;  // zigzag by t
    int tid = threadIdx.x;
    int u0 = uc * 128;
    __shared__ float hsh[128];

    if (tid < 128) {
        float hv = g_hnewT[(u0 + tid) * Nn + n];
        __nv_bfloat16 hi, lo;
        bf16split(hv, &hi, &lo);
        g_acth[(size_t)n * KR + u0 + tid] = hi;
        g_actl[(size_t)n * KR + u0 + tid] = lo;
        hsh[tid] = hv;
    }
    __syncthreads();

    if (tid < Pp) {
        // contiguous 128-u strip: 16 x uint4 (8 bf16 each)
        const uint4* ap = (const uint4*)(g_Atbf + ((size_t)n * Pp + tid) * Hh + u0);
        float acc = 0.f;
#pragma unroll
        for (int i = 0; i < 16; i++) {
            uint4 v = ap[i];
            const __nv_bfloat162* b2 = (const __nv_bfloat162*)&v;
#pragma unroll
            for (int j = 0; j < 4; j++) {
                float2 f = __bfloat1622float2(b2[j]);
                acc += f.x * hsh[i * 8 + 2 * j] + f.y * hsh[i * 8 + 2 * j + 1];
            }
        }
        g_sp[n][uc][tid] = acc;
    }
}

// ================= attn: softmax + weighted sum (transposed bf16 A, coalesced) =================
__global__ __launch_bounds__(256) void attnsum_kernel(int t) {
    int uc = blockIdx.x;
    int n = (t & 1) ? (Nn - 1 - (int)blockIdx.y) : (int)blockIdx.y;  // zigzag by t
    int tid = threadIdx.x;
    __shared__ __align__(16) float w[Pp];
    __shared__ float red[256];

    float myscore = 0.f, s = -3.4e38f;
    if (tid < Pp) {
        float acc = 0.f;
#pragma unroll
        for (int q = 0; q < 8; q++) acc += g_sp[n][q][tid];
        myscore = acc * 0.03125f;
        s = myscore;
    }
    red[tid] = s;
    __syncthreads();
    for (int off = 128; off > 0; off >>= 1) {
        if (tid < off) red[tid] = fmaxf(red[tid], red[tid + off]);
        __syncthreads();
    }
    float mx = red[0];
    __syncthreads();
    float e = (tid < Pp) ? expf(myscore - mx) : 0.f;
    red[tid] = e;
    __syncthreads();
    for (int off = 128; off > 0; off >>= 1) {
        if (tid < off) red[tid] += red[tid + off];
        __syncthreads();
    }
    float inv = 1.f / red[0];
    if (tid < Pp) w[tid] = e * inv;
    __syncthreads();

    // attn[u] = sum_p w[p] * At[n][p][u]  (coalesced across tid)
    int u = uc * 256 + tid;
    const __nv_bfloat16* ap = g_Atbf + (size_t)n * Pp * Hh + u;
    float acc = 0.f;
#pragma unroll 4
    for (int p = 0; p < Pp; p++) {
        acc += w[p] * __bfloat162float(ap[(size_t)p * Hh]);
    }
    __nv_bfloat16 hi, lo;
    bf16split(acc, &hi, &lo);
    g_acth[(size_t)n * KR + 1024 + u] = hi;
    g_actl[(size_t)n * KR + 1024 + u] = lo;
}

// ================= gates: [h|attn]@Wf + xproj_t, fused LSTM =================
__global__ __launch_bounds__(256) void gates_mma_kernel(float* __restrict__ out, int t) {
    extern __shared__ __align__(1024) char dsm[];
    int tid = threadIdx.x;
    int w = tid >> 5, lane = tid & 31;
    int j0 = blockIdx.x * 32;

    float acc[4][4];
    {
        int row0 = w * 16 + (lane >> 2);
#pragma unroll
        for (int j = 0; j < 4; j++) {
            int col = j0 + j * 8 + (lane & 3) * 2;
            float2 v0 = __ldcs((const float2*)&g_xp[((size_t)row0 * Tt + t) * G4 + col]);
            float2 v1 = __ldcs((const float2*)&g_xp[((size_t)(row0 + 8) * Tt + t) * G4 + col]);
            acc[j][0] = v0.x; acc[j][1] = v0.y; acc[j][2] = v1.x; acc[j][3] = v1.y;
        }
    }

    mma_mainloop(tid, dsm, acc, KR / KC,
                 g_acth, g_actl, KR,
                 g_Wfh + (size_t)j0 * KR, g_Wfl + (size_t)j0 * KR, KR);

    int q = lane & 3;
    int rbase = w * 16 + (lane >> 2);
#pragma unroll
    for (int j = 0; j < 4; j++) {
        float e0 = __shfl_xor_sync(0xffffffff, acc[j][0], 1);
        float e1 = __shfl_xor_sync(0xffffffff, acc[j][1], 1);
        float e2 = __shfl_xor_sync(0xffffffff, acc[j][2], 1);
        float e3 = __shfl_xor_sync(0xffffffff, acc[j][3], 1);
        int u = blockIdx.x * 8 + 2 * j + (q >> 1);
        int m;
        float ai, af, ao, ag;
        if ((q & 1) == 0) {
            m = rbase;
            ai = acc[j][0]; af = acc[j][1]; ao = e0; ag = e1;
        } else {
            m = rbase + 8;
            ai = e2; af = e3; ao = acc[j][2]; ag = acc[j][3];
        }
        float ig = 1.f / (1.f + expf(-ai));
        float fg = 1.f / (1.f + expf(-af));
        float og = 1.f / (1.f + expf(-ao));
        float gg = tanhf(ag);
        float cn = fg * g_cT[u * Nn + m] + ig * gg;
        float hn = og * tanhf(cn);
        g_cT[u * Nn + m] = cn;
        g_hnewT[u * Nn + m] = hn;
        __stcs(&out[((size_t)m * Tt + t) * Hh + u], hn);
    }
}

extern "C" void kernel_launch(void* const* d_in, const int* in_sizes, int n_in,
                              void* d_out, int out_size) {
    const float* x  = (const float*)d_in[0];
    const float* A  = (const float*)d_in[1];
    const float* Wx = (const float*)d_in[2];
    const float* Wh = (const float*)d_in[3];
    const float* Wa = (const float*)d_in[4];
    const float* b  = (const float*)d_in[5];
    float* out = (float*)d_out;

    cudaFuncSetAttribute(gates_mma_kernel, cudaFuncAttributeMaxDynamicSharedMemorySize, NSTG * STB);
    cudaFuncSetAttribute(xproj_kernel, cudaFuncAttributeMaxDynamicSharedMemorySize, NSTG * STB);

    permute_kernel<<<2048, 256>>>(Wx, Wh, Wa, b);
    xsplit_kernel<<<4096, 256>>>(x);
    a2bft_kernel<<<dim3(32, 128), 256>>>(A);
    init_kernel<<<Nn, 256>>>(A);
    xproj_kernel<<<dim3(G4 / 32, MX / 128), 256, NSTG * STB>>>();
    for (int t = 0; t < Tt; t++) {
        scores_kernel<<<dim3(8, Nn), 256>>>(t);
        attnsum_kernel<<<dim3(4, Nn), 256>>>(t);
        gates_mma_kernel<<<G4 / 32, 256, NSTG * STB>>>(out, t);
    }
}

// round 14
// speedup vs baseline: 1.0265x; 1.0265x over previous
#include <cuda_runtime.h>
#include <cuda_bf16.h>
#include <math.h>
#include <stdint.h>

#define Nn 128
#define Tt 256
#define Dd 1024
#define Hh 1024
#define G4 4096
#define Pp 196
#define KR 2048   // recurrent K: [h | attn]
#define MX (Nn * Tt)

// ================= device scratch (static) =================
__device__ __align__(16) __nv_bfloat16 g_Wxh[(size_t)G4 * Dd];
__device__ __align__(16) __nv_bfloat16 g_Wxl[(size_t)G4 * Dd];
__device__ __align__(16) __nv_bfloat16 g_Wfh[(size_t)G4 * KR];
__device__ __align__(16) __nv_bfloat16 g_Wfl[(size_t)G4 * KR];
__device__ __align__(16) __nv_bfloat16 g_xh[(size_t)MX * Dd];
__device__ __align__(16) __nv_bfloat16 g_xl[(size_t)MX * Dd];
__device__ float g_xp[(size_t)MX * G4];
__device__ __align__(16) __nv_bfloat16 g_Atbf[(size_t)Nn * Pp * Hh];  // bf16 A transposed [n][p][u]
__device__ __align__(16) __nv_bfloat16 g_acth[(size_t)Nn * KR];
__device__ __align__(16) __nv_bfloat16 g_actl[(size_t)Nn * KR];
__device__ float g_bf[G4];
__device__ float g_hnewT[Hh * Nn];
__device__ float g_cT[Hh * Nn];
__device__ float g_sp[Nn][8][Pp];

// ================= helpers =================
__device__ __forceinline__ uint32_t smem_u32(const void* p) {
    uint32_t a;
    asm("{ .reg .u64 t; cvta.to.shared.u64 t, %1; cvt.u32.u64 %0, t; }" : "=r"(a) : "l"(p));
    return a;
}
__device__ __forceinline__ void cp16(uint32_t dst, const void* src) {
    asm volatile("cp.async.cg.shared.global [%0], [%1], 16;" :: "r"(dst), "l"(src));
}
__device__ __forceinline__ void cpcommit() { asm volatile("cp.async.commit_group;" ::: "memory"); }
template <int N> __device__ __forceinline__ void cpwait() {
    asm volatile("cp.async.wait_group %0;" :: "n"(N) : "memory");
}
__device__ __forceinline__ void ldsm_x4(uint32_t& r0, uint32_t& r1, uint32_t& r2, uint32_t& r3,
                                        uint32_t addr) {
    asm volatile("ldmatrix.sync.aligned.m8n8.x4.shared.b16 {%0,%1,%2,%3}, [%4];"
                 : "=r"(r0), "=r"(r1), "=r"(r2), "=r"(r3) : "r"(addr));
}
__device__ __forceinline__ void mma16816(float* d, const uint32_t* a, const uint32_t* b) {
    asm volatile(
        "mma.sync.aligned.m16n8k16.row.col.f32.bf16.bf16.f32 "
        "{%0,%1,%2,%3}, {%4,%5,%6,%7}, {%8,%9}, {%0,%1,%2,%3};"
        : "+f"(d[0]), "+f"(d[1]), "+f"(d[2]), "+f"(d[3])
        : "r"(a[0]), "r"(a[1]), "r"(a[2]), "r"(a[3]), "r"(b[0]), "r"(b[1]));
}
#define SWZ128(o) ((o) ^ (((o) >> 3) & 0x70))

__device__ __forceinline__ void bf16split(float v, __nv_bfloat16* hi, __nv_bfloat16* lo) {
    __nv_bfloat16 h = __float2bfloat16(v);
    *hi = h;
    *lo = __float2bfloat16(v - __bfloat162float(h));
}

// ================= one-time kernels =================
__global__ __launch_bounds__(256) void permute_kernel(
    const float* __restrict__ Wx, const float* __restrict__ Wh,
    const float* __restrict__ Wa, const float* __restrict__ b) {
    size_t total = (size_t)G4 * 3072;
    size_t stride = (size_t)gridDim.x * blockDim.x;
    for (size_t idx = (size_t)blockIdx.x * blockDim.x + threadIdx.x; idx < total; idx += stride) {
        int j = (int)(idx / 3072);
        int k = (int)(idx - (size_t)j * 3072);
        int src = (j & 3) * 1024 + (j >> 2);
        __nv_bfloat16 hi, lo;
        if (k < 1024) {
            bf16split(Wx[(size_t)k * G4 + src], &hi, &lo);
            g_Wxh[(size_t)j * Dd + k] = hi;
            g_Wxl[(size_t)j * Dd + k] = lo;
        } else {
            float v = (k < 2048) ? Wh[(size_t)(k - 1024) * G4 + src]
                                 : Wa[(size_t)(k - 2048) * G4 + src];
            bf16split(v, &hi, &lo);
            g_Wfh[(size_t)j * KR + (k - 1024)] = hi;
            g_Wfl[(size_t)j * KR + (k - 1024)] = lo;
        }
        if (k == 0) g_bf[j] = b[src];
    }
}

__global__ __launch_bounds__(256) void xsplit_kernel(const float* __restrict__ x) {
    size_t total = (size_t)MX * Dd;
    size_t stride = (size_t)gridDim.x * blockDim.x;
    for (size_t i = (size_t)blockIdx.x * blockDim.x + threadIdx.x; i < total; i += stride) {
        __nv_bfloat16 hi, lo;
        bf16split(x[i], &hi, &lo);
        g_xh[i] = hi;
        g_xl[i] = lo;
    }
}

// one-time: A[n][u][p] fp32 -> Atbf[n][p][u] bf16 (tile transpose)
__global__ __launch_bounds__(256) void a2bft_kernel(const float* __restrict__ A) {
    __shared__ float tile[32][197];
    int n = blockIdx.y;
    int u0 = blockIdx.x * 32;
    const float* src = A + ((size_t)n * Hh + u0) * Pp;
    for (int i = threadIdx.x; i < 32 * Pp; i += 256) {
        int u = i / Pp, p = i - u * Pp;
        tile[u][p] = src[(size_t)u * Pp + p];
    }
    __syncthreads();
    __nv_bfloat16* dst = g_Atbf + (size_t)n * Pp * Hh + u0;
    for (int i = threadIdx.x; i < 32 * Pp; i += 256) {
        int u = i & 31, p = i >> 5;
        dst[(size_t)p * Hh + u] = __float2bfloat16(tile[u][p]);
    }
}

__global__ __launch_bounds__(256) void init_kernel(const float* __restrict__ A) {
    int n = blockIdx.x;
    for (int u = threadIdx.x; u < Hh; u += blockDim.x) {
        const float4* r = (const float4*)(A + ((size_t)n * Hh + u) * Pp);
        float s = 0.f;
#pragma unroll
        for (int i = 0; i < 49; i++) {
            float4 v = r[i];
            s += v.x + v.y + v.z + v.w;
        }
        float m = s * (1.f / 196.f);
        g_hnewT[u * Nn + n] = m;
        g_cT[u * Nn + n] = m;
    }
}

// ================= generic split-bf16x3 mma mainloop (KC=64, SW128) =================
#define KC 64
#define STB 40960
#define NSTG 3

__device__ __forceinline__ void load_chunk_g(
    int tid, int c, char* buf,
    const __nv_bfloat16* Ah, const __nv_bfloat16* Al, int lda,
    const __nv_bfloat16* Bh, const __nv_bfloat16* Bl, int ldb) {
    uint32_t sbase = smem_u32(buf);
#pragma unroll
    for (int it = 0; it < 4; it++) {
        int id = tid + it * 256;           // 0..1023 : 128 rows x 8 16B-chunks
        int m = id >> 3, kc = id & 7;
        uint32_t off = SWZ128((uint32_t)m * 128 + (uint32_t)kc * 16);
        size_t gidx = (size_t)m * lda + (size_t)c * KC + kc * 8;
        cp16(sbase + off, Ah + gidx);
        cp16(sbase + 16384 + off, Al + gidx);
    }
    {
        int nrow = tid >> 3, kc = tid & 7;  // 256 = 32 rows x 8 chunks
        uint32_t off = SWZ128((uint32_t)nrow * 128 + (uint32_t)kc * 16);
        size_t gidx = (size_t)nrow * ldb + (size_t)c * KC + kc * 8;
        cp16(sbase + 32768 + off, Bh + gidx);
        cp16(sbase + 36864 + off, Bl + gidx);
    }
    cpcommit();
}

__device__ __forceinline__ void mma_mainloop(
    int tid, char* dsm, float acc[4][4], int nch,
    const __nv_bfloat16* Ah, const __nv_bfloat16* Al, int lda,
    const __nv_bfloat16* Bh, const __nv_bfloat16* Bl, int ldb) {
    int w = tid >> 5, lane = tid & 31;
    load_chunk_g(tid, 0, dsm, Ah, Al, lda, Bh, Bl, ldb);
    load_chunk_g(tid, 1, dsm + STB, Ah, Al, lda, Bh, Bl, ldb);
    for (int c = 0; c < nch; c++) {
        if (c + 1 < nch) cpwait<1>(); else cpwait<0>();
        __syncthreads();
        uint32_t sbase = smem_u32(dsm + (c % NSTG) * STB);
        int arow = w * 16 + (lane & 15);
#pragma unroll
        for (int ks = 0; ks < 4; ks++) {
            int ak = ks * 16 + ((lane & 16) ? 8 : 0);
            uint32_t aoff = SWZ128((uint32_t)arow * 128 + (uint32_t)ak * 2);
            uint32_t ah[4], al[4];
            ldsm_x4(ah[0], ah[1], ah[2], ah[3], sbase + aoff);
            ldsm_x4(al[0], al[1], al[2], al[3], sbase + 16384 + aoff);
            uint32_t bh[8], bl[8];
            int bk = ks * 16 + ((lane & 8) ? 8 : 0);
#pragma unroll
            for (int jj = 0; jj < 2; jj++) {
                int nrow = jj * 16 + ((lane & 16) ? 8 : 0) + (lane & 7);
                uint32_t boff = SWZ128((uint32_t)nrow * 128 + (uint32_t)bk * 2);
                ldsm_x4(bh[4 * jj], bh[4 * jj + 1], bh[4 * jj + 2], bh[4 * jj + 3],
                        sbase + 32768 + boff);
                ldsm_x4(bl[4 * jj], bl[4 * jj + 1], bl[4 * jj + 2], bl[4 * jj + 3],
                        sbase + 36864 + boff);
            }
#pragma unroll
            for (int j = 0; j < 4; j++) {
                mma16816(acc[j], ah, &bh[2 * j]);
                mma16816(acc[j], ah, &bl[2 * j]);
                mma16816(acc[j], al, &bh[2 * j]);
            }
        }
        if (c + 2 < nch)
            load_chunk_g(tid, c + 2, dsm + ((c + 2) % NSTG) * STB, Ah, Al, lda, Bh, Bl, ldb);
    }
}

// ================= one-time: xproj = x @ Wx + b =================
__global__ __launch_bounds__(256) void xproj_kernel() {
    extern __shared__ __align__(1024) char dsm[];
    int tid = threadIdx.x;
    int w = tid >> 5, lane = tid & 31;
    int j0 = blockIdx.x * 32;
    int m0 = blockIdx.y * 128;

    float acc[4][4];
#pragma unroll
    for (int j = 0; j < 4; j++)
#pragma unroll
        for (int r = 0; r < 4; r++) acc[j][r] = 0.f;

    mma_mainloop(tid, dsm, acc, Dd / KC,
                 g_xh + (size_t)m0 * Dd, g_xl + (size_t)m0 * Dd, Dd,
                 g_Wxh + (size_t)j0 * Dd, g_Wxl + (size_t)j0 * Dd, Dd);

    int row0 = m0 + w * 16 + (lane >> 2);
#pragma unroll
    for (int j = 0; j < 4; j++) {
        int col = j0 + j * 8 + (lane & 3) * 2;
        float2 bb = *(const float2*)&g_bf[col];
        *(float2*)&g_xp[(size_t)row0 * G4 + col] = make_float2(acc[j][0] + bb.x, acc[j][1] + bb.y);
        *(float2*)&g_xp[(size_t)(row0 + 8) * G4 + col] = make_float2(acc[j][2] + bb.x, acc[j][3] + bb.y);
    }
}

// ================= scores: grid (8,128); warp-per-p over transposed bf16 A =================
__global__ __launch_bounds__(256) void scores_kernel(int t) {
    int uc = blockIdx.x;
    int n = (t & 1) ? (Nn - 1 - (int)blockIdx.y) : (int)blockIdx.y;  // zigzag by t
    int tid = threadIdx.x;
    int w = tid >> 5, lane = tid & 31;
    int u0 = uc * 128;
    __shared__ float hsh[128];

    if (tid < 128) {
        float hv = g_hnewT[(u0 + tid) * Nn + n];
        __nv_bfloat16 hi, lo;
        bf16split(hv, &hi, &lo);
        g_acth[(size_t)n * KR + u0 + tid] = hi;
        g_actl[(size_t)n * KR + u0 + tid] = lo;
        hsh[tid] = hv;
    }
    __syncthreads();

    // lane's 4 h values (reused for all p)
    float h0 = hsh[lane * 4 + 0];
    float h1 = hsh[lane * 4 + 1];
    float h2 = hsh[lane * 4 + 2];
    float h3 = hsh[lane * 4 + 3];

    const __nv_bfloat16* base = g_Atbf + (size_t)n * Pp * Hh + u0;
    // warp-per-p: lane-consecutive uint2 (4 bf16) = one coalesced 256B row read
    for (int p = w; p < Pp; p += 8) {
        uint2 v = *(const uint2*)(base + (size_t)p * Hh + lane * 4);
        const __nv_bfloat162* b2 = (const __nv_bfloat162*)&v;
        float2 f0 = __bfloat1622float2(b2[0]);
        float2 f1 = __bfloat1622float2(b2[1]);
        float acc = f0.x * h0 + f0.y * h1 + f1.x * h2 + f1.y * h3;
#pragma unroll
        for (int o = 16; o > 0; o >>= 1) acc += __shfl_xor_sync(0xffffffff, acc, o);
        if (lane == 0) g_sp[n][uc][p] = acc;
    }
}

// ================= attn: softmax + weighted sum (transposed bf16 A, coalesced) =================
__global__ __launch_bounds__(256) void attnsum_kernel(int t) {
    int uc = blockIdx.x;
    int n = (t & 1) ? (Nn - 1 - (int)blockIdx.y) : (int)blockIdx.y;  // zigzag by t
    int tid = threadIdx.x;
    __shared__ __align__(16) float w[Pp];
    __shared__ float red[256];

    float myscore = 0.f, s = -3.4e38f;
    if (tid < Pp) {
        float acc = 0.f;
#pragma unroll
        for (int q = 0; q < 8; q++) acc += g_sp[n][q][tid];
        myscore = acc * 0.03125f;
        s = myscore;
    }
    red[tid] = s;
    __syncthreads();
    for (int off = 128; off > 0; off >>= 1) {
        if (tid < off) red[tid] = fmaxf(red[tid], red[tid + off]);
        __syncthreads();
    }
    float mx = red[0];
    __syncthreads();
    float e = (tid < Pp) ? expf(myscore - mx) : 0.f;
    red[tid] = e;
    __syncthreads();
    for (int off = 128; off > 0; off >>= 1) {
        if (tid < off) red[tid] += red[tid + off];
        __syncthreads();
    }
    float inv = 1.f / red[0];
    if (tid < Pp) w[tid] = e * inv;
    __syncthreads();

    // attn[u] = sum_p w[p] * At[n][p][u]  (coalesced across tid)
    int u = uc * 256 + tid;
    const __nv_bfloat16* ap = g_Atbf + (size_t)n * Pp * Hh + u;
    float acc = 0.f;
#pragma unroll 4
    for (int p = 0; p < Pp; p++) {
        acc += w[p] * __bfloat162float(ap[(size_t)p * Hh]);
    }
    __nv_bfloat16 hi, lo;
    bf16split(acc, &hi, &lo);
    g_acth[(size_t)n * KR + 1024 + u] = hi;
    g_actl[(size_t)n * KR + 1024 + u] = lo;
}

// ================= gates: [h|attn]@Wf + xproj_t, fused LSTM =================
__global__ __launch_bounds__(256) void gates_mma_kernel(float* __restrict__ out, int t) {
    extern __shared__ __align__(1024) char dsm[];
    int tid = threadIdx.x;
    int w = tid >> 5, lane = tid & 31;
    int j0 = blockIdx.x * 32;

    float acc[4][4];
    {
        int row0 = w * 16 + (lane >> 2);
#pragma unroll
        for (int j = 0; j < 4; j++) {
            int col = j0 + j * 8 + (lane & 3) * 2;
            float2 v0 = __ldcs((const float2*)&g_xp[((size_t)row0 * Tt + t) * G4 + col]);
            float2 v1 = __ldcs((const float2*)&g_xp[((size_t)(row0 + 8) * Tt + t) * G4 + col]);
            acc[j][0] = v0.x; acc[j][1] = v0.y; acc[j][2] = v1.x; acc[j][3] = v1.y;
        }
    }

    mma_mainloop(tid, dsm, acc, KR / KC,
                 g_acth, g_actl, KR,
                 g_Wfh + (size_t)j0 * KR, g_Wfl + (size_t)j0 * KR, KR);

    int q = lane & 3;
    int rbase = w * 16 + (lane >> 2);
#pragma unroll
    for (int j = 0; j < 4; j++) {
        float e0 = __shfl_xor_sync(0xffffffff, acc[j][0], 1);
        float e1 = __shfl_xor_sync(0xffffffff, acc[j][1], 1);
        float e2 = __shfl_xor_sync(0xffffffff, acc[j][2], 1);
        float e3 = __shfl_xor_sync(0xffffffff, acc[j][3], 1);
        int u = blockIdx.x * 8 + 2 * j + (q >> 1);
        int m;
        float ai, af, ao, ag;
        if ((q & 1) == 0) {
            m = rbase;
            ai = acc[j][0]; af = acc[j][1]; ao = e0; ag = e1;
        } else {
            m = rbase + 8;
            ai = e2; af = e3; ao = acc[j][2]; ag = acc[j][3];
        }
        float ig = 1.f / (1.f + expf(-ai));
        float fg = 1.f / (1.f + expf(-af));
        float og = 1.f / (1.f + expf(-ao));
        float gg = tanhf(ag);
        float cn = fg * g_cT[u * Nn + m] + ig * gg;
        float hn = og * tanhf(cn);
        g_cT[u * Nn + m] = cn;
        g_hnewT[u * Nn + m] = hn;
        __stcs(&out[((size_t)m * Tt + t) * Hh + u], hn);
    }
}

extern "C" void kernel_launch(void* const* d_in, const int* in_sizes, int n_in,
                              void* d_out, int out_size) {
    const float* x  = (const float*)d_in[0];
    const float* A  = (const float*)d_in[1];
    const float* Wx = (const float*)d_in[2];
    const float* Wh = (const float*)d_in[3];
    const float* Wa = (const float*)d_in[4];
    const float* b  = (const float*)d_in[5];
    float* out = (float*)d_out;

    cudaFuncSetAttribute(gates_mma_kernel, cudaFuncAttributeMaxDynamicSharedMemorySize, NSTG * STB);
    cudaFuncSetAttribute(xproj_kernel, cudaFuncAttributeMaxDynamicSharedMemorySize, NSTG * STB);

    permute_kernel<<<2048, 256>>>(Wx, Wh, Wa, b);
    xsplit_kernel<<<4096, 256>>>(x);
    a2bft_kernel<<<dim3(32, 128), 256>>>(A);
    init_kernel<<<Nn, 256>>>(A);
    xproj_kernel<<<dim3(G4 / 32, MX / 128), 256, NSTG * STB>>>();
    for (int t = 0; t < Tt; t++) {
        scores_kernel<<<dim3(8, Nn), 256>>>(t);
        attnsum_kernel<<<dim3(4, Nn), 256>>>(t);
        gates_mma_kernel<<<G4 / 32, 256, NSTG * STB>>>(out, t);
    }
}

// round 15
// speedup vs baseline: 1.1834x; 1.1528x over previous
#include <cuda_runtime.h>
#include <cuda_bf16.h>
#include <math.h>
#include <stdint.h>

#define Nn 128
#define Tt 256
#define Dd 1024
#define Hh 1024
#define G4 4096
#define Pp 196
#define KR 2048   // recurrent K: [h | attn]
#define MX (Nn * Tt)

// ================= device scratch (static) =================
__device__ __align__(16) __nv_bfloat16 g_Wxh[(size_t)G4 * Dd];
__device__ __align__(16) __nv_bfloat16 g_Wxl[(size_t)G4 * Dd];
__device__ __align__(16) __nv_bfloat16 g_Wfh[(size_t)G4 * KR];
__device__ __align__(16) __nv_bfloat16 g_Wfl[(size_t)G4 * KR];
__device__ __align__(16) __nv_bfloat16 g_xh[(size_t)MX * Dd];
__device__ __align__(16) __nv_bfloat16 g_xl[(size_t)MX * Dd];
__device__ float g_xp[(size_t)MX * G4];
__device__ __align__(16) __nv_bfloat16 g_Abf[(size_t)Nn * Hh * Pp];  // bf16 A row-major (R11 layout)
__device__ __align__(16) __nv_bfloat16 g_acth[(size_t)Nn * KR];
__device__ __align__(16) __nv_bfloat16 g_actl[(size_t)Nn * KR];
__device__ float g_bf[G4];
__device__ float g_hnewT[Hh * Nn];
__device__ float g_cT[Hh * Nn];
__device__ float g_sp[Nn][4][Pp];
__device__ int g_cnt[Nn * 2];   // per-n arrival counters, ping-pong by t parity

// ================= helpers =================
__device__ __forceinline__ uint32_t smem_u32(const void* p) {
    uint32_t a;
    asm("{ .reg .u64 t; cvta.to.shared.u64 t, %1; cvt.u32.u64 %0, t; }" : "=r"(a) : "l"(p));
    return a;
}
__device__ __forceinline__ void cp16(uint32_t dst, const void* src) {
    asm volatile("cp.async.cg.shared.global [%0], [%1], 16;" :: "r"(dst), "l"(src));
}
__device__ __forceinline__ void cpcommit() { asm volatile("cp.async.commit_group;" ::: "memory"); }
template <int N> __device__ __forceinline__ void cpwait() {
    asm volatile("cp.async.wait_group %0;" :: "n"(N) : "memory");
}
__device__ __forceinline__ void ldsm_x4(uint32_t& r0, uint32_t& r1, uint32_t& r2, uint32_t& r3,
                                        uint32_t addr) {
    asm volatile("ldmatrix.sync.aligned.m8n8.x4.shared.b16 {%0,%1,%2,%3}, [%4];"
                 : "=r"(r0), "=r"(r1), "=r"(r2), "=r"(r3) : "r"(addr));
}
__device__ __forceinline__ void mma16816(float* d, const uint32_t* a, const uint32_t* b) {
    asm volatile(
        "mma.sync.aligned.m16n8k16.row.col.f32.bf16.bf16.f32 "
        "{%0,%1,%2,%3}, {%4,%5,%6,%7}, {%8,%9}, {%0,%1,%2,%3};"
        : "+f"(d[0]), "+f"(d[1]), "+f"(d[2]), "+f"(d[3])
        : "r"(a[0]), "r"(a[1]), "r"(a[2]), "r"(a[3]), "r"(b[0]), "r"(b[1]));
}
#define SWZ128(o) ((o) ^ (((o) >> 3) & 0x70))

__device__ __forceinline__ void bf16split(float v, __nv_bfloat16* hi, __nv_bfloat16* lo) {
    __nv_bfloat16 h = __float2bfloat16(v);
    *hi = h;
    *lo = __float2bfloat16(v - __bfloat162float(h));
}

// ================= one-time kernels =================
__global__ __launch_bounds__(256) void permute_kernel(
    const float* __restrict__ Wx, const float* __restrict__ Wh,
    const float* __restrict__ Wa, const float* __restrict__ b) {
    size_t total = (size_t)G4 * 3072;
    size_t stride = (size_t)gridDim.x * blockDim.x;
    for (size_t idx = (size_t)blockIdx.x * blockDim.x + threadIdx.x; idx < total; idx += stride) {
        int j = (int)(idx / 3072);
        int k = (int)(idx - (size_t)j * 3072);
        int src = (j & 3) * 1024 + (j >> 2);
        __nv_bfloat16 hi, lo;
        if (k < 1024) {
            bf16split(Wx[(size_t)k * G4 + src], &hi, &lo);
            g_Wxh[(size_t)j * Dd + k] = hi;
            g_Wxl[(size_t)j * Dd + k] = lo;
        } else {
            float v = (k < 2048) ? Wh[(size_t)(k - 1024) * G4 + src]
                                 : Wa[(size_t)(k - 2048) * G4 + src];
            bf16split(v, &hi, &lo);
            g_Wfh[(size_t)j * KR + (k - 1024)] = hi;
            g_Wfl[(size_t)j * KR + (k - 1024)] = lo;
        }
        if (k == 0) g_bf[j] = b[src];
    }
}

__global__ __launch_bounds__(256) void xsplit_kernel(const float* __restrict__ x) {
    size_t total = (size_t)MX * Dd;
    size_t stride = (size_t)gridDim.x * blockDim.x;
    for (size_t i = (size_t)blockIdx.x * blockDim.x + threadIdx.x; i < total; i += stride) {
        __nv_bfloat16 hi, lo;
        bf16split(x[i], &hi, &lo);
        g_xh[i] = hi;
        g_xl[i] = lo;
    }
}

__global__ __launch_bounds__(256) void a2bf_kernel(const float* __restrict__ A) {
    size_t total = (size_t)Nn * Hh * Pp;
    size_t stride = (size_t)gridDim.x * blockDim.x;
    for (size_t i = (size_t)blockIdx.x * blockDim.x + threadIdx.x; i < total; i += stride)
        g_Abf[i] = __float2bfloat16(A[i]);
}

__global__ __launch_bounds__(256) void init_kernel(const float* __restrict__ A) {
    int n = blockIdx.x;
    if (threadIdx.x < 2) g_cnt[n * 2 + threadIdx.x] = 0;
    for (int u = threadIdx.x; u < Hh; u += blockDim.x) {
        const float4* r = (const float4*)(A + ((size_t)n * Hh + u) * Pp);
        float s = 0.f;
#pragma unroll
        for (int i = 0; i < 49; i++) {
            float4 v = r[i];
            s += v.x + v.y + v.z + v.w;
        }
        float m = s * (1.f / 196.f);
        g_hnewT[u * Nn + n] = m;
        g_cT[u * Nn + n] = m;
    }
}

// ================= generic split-bf16x3 mma mainloop (KC=64, SW128) =================
#define KC 64
#define STB 40960
#define NSTG 3

__device__ __forceinline__ void load_chunk_g(
    int tid, int c, char* buf,
    const __nv_bfloat16* Ah, const __nv_bfloat16* Al, int lda,
    const __nv_bfloat16* Bh, const __nv_bfloat16* Bl, int ldb) {
    uint32_t sbase = smem_u32(buf);
#pragma unroll
    for (int it = 0; it < 4; it++) {
        int id = tid + it * 256;           // 0..1023 : 128 rows x 8 16B-chunks
        int m = id >> 3, kc = id & 7;
        uint32_t off = SWZ128((uint32_t)m * 128 + (uint32_t)kc * 16);
        size_t gidx = (size_t)m * lda + (size_t)c * KC + kc * 8;
        cp16(sbase + off, Ah + gidx);
        cp16(sbase + 16384 + off, Al + gidx);
    }
    {
        int nrow = tid >> 3, kc = tid & 7;  // 256 = 32 rows x 8 chunks
        uint32_t off = SWZ128((uint32_t)nrow * 128 + (uint32_t)kc * 16);
        size_t gidx = (size_t)nrow * ldb + (size_t)c * KC + kc * 8;
        cp16(sbase + 32768 + off, Bh + gidx);
        cp16(sbase + 36864 + off, Bl + gidx);
    }
    cpcommit();
}

__device__ __forceinline__ void mma_mainloop(
    int tid, char* dsm, float acc[4][4], int nch,
    const __nv_bfloat16* Ah, const __nv_bfloat16* Al, int lda,
    const __nv_bfloat16* Bh, const __nv_bfloat16* Bl, int ldb) {
    int w = tid >> 5, lane = tid & 31;
    load_chunk_g(tid, 0, dsm, Ah, Al, lda, Bh, Bl, ldb);
    load_chunk_g(tid, 1, dsm + STB, Ah, Al, lda, Bh, Bl, ldb);
    for (int c = 0; c < nch; c++) {
        if (c + 1 < nch) cpwait<1>(); else cpwait<0>();
        __syncthreads();
        uint32_t sbase = smem_u32(dsm + (c % NSTG) * STB);
        int arow = w * 16 + (lane & 15);
#pragma unroll
        for (int ks = 0; ks < 4; ks++) {
            int ak = ks * 16 + ((lane & 16) ? 8 : 0);
            uint32_t aoff = SWZ128((uint32_t)arow * 128 + (uint32_t)ak * 2);
            uint32_t ah[4], al[4];
            ldsm_x4(ah[0], ah[1], ah[2], ah[3], sbase + aoff);
            ldsm_x4(al[0], al[1], al[2], al[3], sbase + 16384 + aoff);
            uint32_t bh[8], bl[8];
            int bk = ks * 16 + ((lane & 8) ? 8 : 0);
#pragma unroll
            for (int jj = 0; jj < 2; jj++) {
                int nrow = jj * 16 + ((lane & 16) ? 8 : 0) + (lane & 7);
                uint32_t boff = SWZ128((uint32_t)nrow * 128 + (uint32_t)bk * 2);
                ldsm_x4(bh[4 * jj], bh[4 * jj + 1], bh[4 * jj + 2], bh[4 * jj + 3],
                        sbase + 32768 + boff);
                ldsm_x4(bl[4 * jj], bl[4 * jj + 1], bl[4 * jj + 2], bl[4 * jj + 3],
                        sbase + 36864 + boff);
            }
#pragma unroll
            for (int j = 0; j < 4; j++) {
                mma16816(acc[j], ah, &bh[2 * j]);
                mma16816(acc[j], ah, &bl[2 * j]);
                mma16816(acc[j], al, &bh[2 * j]);
            }
        }
        if (c + 2 < nch)
            load_chunk_g(tid, c + 2, dsm + ((c + 2) % NSTG) * STB, Ah, Al, lda, Bh, Bl, ldb);
    }
}

// ================= one-time: xproj = x @ Wx + b =================
__global__ __launch_bounds__(256) void xproj_kernel() {
    extern __shared__ __align__(1024) char dsm[];
    int tid = threadIdx.x;
    int w = tid >> 5, lane = tid & 31;
    int j0 = blockIdx.x * 32;
    int m0 = blockIdx.y * 128;

    float acc[4][4];
#pragma unroll
    for (int j = 0; j < 4; j++)
#pragma unroll
        for (int r = 0; r < 4; r++) acc[j][r] = 0.f;

    mma_mainloop(tid, dsm, acc, Dd / KC,
                 g_xh + (size_t)m0 * Dd, g_xl + (size_t)m0 * Dd, Dd,
                 g_Wxh + (size_t)j0 * Dd, g_Wxl + (size_t)j0 * Dd, Dd);

    int row0 = m0 + w * 16 + (lane >> 2);
#pragma unroll
    for (int j = 0; j < 4; j++) {
        int col = j0 + j * 8 + (lane & 3) * 2;
        float2 bb = *(const float2*)&g_bf[col];
        *(float2*)&g_xp[(size_t)row0 * G4 + col] = make_float2(acc[j][0] + bb.x, acc[j][1] + bb.y);
        *(float2*)&g_xp[(size_t)(row0 + 8) * G4 + col] = make_float2(acc[j][2] + bb.x, acc[j][3] + bb.y);
    }
}

// ================= fused attention step: scores -> grid handshake -> softmax+sum =======
// grid (4, Nn), 256 threads, ALL 512 blocks resident (launch_bounds(256,4) caps regs).
__global__ __launch_bounds__(256, 4) void attn_step_kernel(int t) {
    int uc = blockIdx.x;
    int n = (t & 1) ? (Nn - 1 - (int)blockIdx.y) : (int)blockIdx.y;  // zigzag by t
    int tid = threadIdx.x;
    int par = t & 1;
    __shared__ float hsh[256];
    __shared__ __align__(16) float w[Pp + 2];
    __shared__ float red[256];

    if (tid == 2) g_cnt[n * 2 + (par ^ 1)] = 0;   // reset other parity for next step

    // ---- phase 1: commit h chunk, partial scores over this block's 256 u ----
    int u0 = uc * 256;
    float hv = g_hnewT[(u0 + tid) * Nn + n];
    {
        __nv_bfloat16 hi, lo;
        bf16split(hv, &hi, &lo);
        g_acth[(size_t)n * KR + u0 + tid] = hi;
        g_actl[(size_t)n * KR + u0 + tid] = lo;
    }
    hsh[tid] = hv;
    __syncthreads();

    if (tid < Pp) {
        const __nv_bfloat16* ap = g_Abf + ((size_t)n * Hh + u0) * Pp + tid;
        float acc = 0.f;
#pragma unroll 8
        for (int u = 0; u < 256; u++) {
            acc += hsh[u] * __bfloat162float(ap[(size_t)u * Pp]);
        }
        g_sp[n][uc][tid] = acc;
    }
    __syncthreads();

    // ---- grid handshake: wait for all 4 partials of this n ----
    if (tid == 0) {
        __threadfence();
        atomicAdd(&g_cnt[n * 2 + par], 1);
        while (*(volatile int*)&g_cnt[n * 2 + par] < 4) { }
        __threadfence();
    }
    __syncthreads();

    // ---- phase 2: softmax (redundant per block) + weighted sum for this u-chunk ----
    float myscore = 0.f, s = -3.4e38f;
    if (tid < Pp) {
        float acc = g_sp[n][0][tid] + g_sp[n][1][tid] + g_sp[n][2][tid] + g_sp[n][3][tid];
        myscore = acc * 0.03125f;
        s = myscore;
    }
    red[tid] = s;
    __syncthreads();
    for (int off = 128; off > 0; off >>= 1) {
        if (tid < off) red[tid] = fmaxf(red[tid], red[tid + off]);
        __syncthreads();
    }
    float mx = red[0];
    __syncthreads();
    float e = (tid < Pp) ? expf(myscore - mx) : 0.f;
    red[tid] = e;
    __syncthreads();
    for (int off = 128; off > 0; off >>= 1) {
        if (tid < off) red[tid] += red[tid + off];
        __syncthreads();
    }
    float inv = 1.f / red[0];
    if (tid < Pp) w[tid] = e * inv;
    if (tid < 2) w[Pp + tid] = 0.f;
    __syncthreads();

    // attn[u] = Abf[n,u,:] . w   (row-per-thread, L1-cached 392B rows — R11-proven)
    int u = u0 + tid;
    const __nv_bfloat162* Ar = (const __nv_bfloat162*)(g_Abf + ((size_t)n * Hh + u) * Pp);
    float acc = 0.f;
#pragma unroll
    for (int i = 0; i < 98; i++) {
        float2 av = __bfloat1622float2(Ar[i]);
        acc += av.x * w[2 * i] + av.y * w[2 * i + 1];
    }
    __nv_bfloat16 hi, lo;
    bf16split(acc, &hi, &lo);
    g_acth[(size_t)n * KR + 1024 + u] = hi;
    g_actl[(size_t)n * KR + 1024 + u] = lo;
}

// ================= gates: [h|attn]@Wf + xproj_t, fused LSTM =================
__global__ __launch_bounds__(256) void gates_mma_kernel(float* __restrict__ out, int t) {
    extern __shared__ __align__(1024) char dsm[];
    int tid = threadIdx.x;
    int w = tid >> 5, lane = tid & 31;
    int j0 = blockIdx.x * 32;

    float acc[4][4];
    {
        int row0 = w * 16 + (lane >> 2);
#pragma unroll
        for (int j = 0; j < 4; j++) {
            int col = j0 + j * 8 + (lane & 3) * 2;
            float2 v0 = __ldcs((const float2*)&g_xp[((size_t)row0 * Tt + t) * G4 + col]);
            float2 v1 = __ldcs((const float2*)&g_xp[((size_t)(row0 + 8) * Tt + t) * G4 + col]);
            acc[j][0] = v0.x; acc[j][1] = v0.y; acc[j][2] = v1.x; acc[j][3] = v1.y;
        }
    }

    mma_mainloop(tid, dsm, acc, KR / KC,
                 g_acth, g_actl, KR,
                 g_Wfh + (size_t)j0 * KR, g_Wfl + (size_t)j0 * KR, KR);

    int q = lane & 3;
    int rbase = w * 16 + (lane >> 2);
#pragma unroll
    for (int j = 0; j < 4; j++) {
        float e0 = __shfl_xor_sync(0xffffffff, acc[j][0], 1);
        float e1 = __shfl_xor_sync(0xffffffff, acc[j][1], 1);
        float e2 = __shfl_xor_sync(0xffffffff, acc[j][2], 1);
        float e3 = __shfl_xor_sync(0xffffffff, acc[j][3], 1);
        int u = blockIdx.x * 8 + 2 * j + (q >> 1);
        int m;
        float ai, af, ao, ag;
        if ((q & 1) == 0) {
            m = rbase;
            ai = acc[j][0]; af = acc[j][1]; ao = e0; ag = e1;
        } else {
            m = rbase + 8;
            ai = e2; af = e3; ao = acc[j][2]; ag = acc[j][3];
        }
        float ig = 1.f / (1.f + expf(-ai));
        float fg = 1.f / (1.f + expf(-af));
        float og = 1.f / (1.f + expf(-ao));
        float gg = tanhf(ag);
        float cn = fg * g_cT[u * Nn + m] + ig * gg;
        float hn = og * tanhf(cn);
        g_cT[u * Nn + m] = cn;
        g_hnewT[u * Nn + m] = hn;
        __stcs(&out[((size_t)m * Tt + t) * Hh + u], hn);
    }
}

extern "C" void kernel_launch(void* const* d_in, const int* in_sizes, int n_in,
                              void* d_out, int out_size) {
    const float* x  = (const float*)d_in[0];
    const float* A  = (const float*)d_in[1];
    const float* Wx = (const float*)d_in[2];
    const float* Wh = (const float*)d_in[3];
    const float* Wa = (const float*)d_in[4];
    const float* b  = (const float*)d_in[5];
    float* out = (float*)d_out;

    cudaFuncSetAttribute(gates_mma_kernel, cudaFuncAttributeMaxDynamicSharedMemorySize, NSTG * STB);
    cudaFuncSetAttribute(xproj_kernel, cudaFuncAttributeMaxDynamicSharedMemorySize, NSTG * STB);

    permute_kernel<<<2048, 256>>>(Wx, Wh, Wa, b);
    xsplit_kernel<<<4096, 256>>>(x);
    a2bf_kernel<<<4096, 256>>>(A);
    init_kernel<<<Nn, 256>>>(A);
    xproj_kernel<<<dim3(G4 / 32, MX / 128), 256, NSTG * STB>>>();
    for (int t = 0; t < Tt; t++) {
        attn_step_kernel<<<dim3(4, Nn), 256>>>(t);
        gates_mma_kernel<<<G4 / 32, 256, NSTG * STB>>>(out, t);
    }
}

// round 16
// speedup vs baseline: 1.2213x; 1.0321x over previous
#include <cuda_runtime.h>
#include <cuda_bf16.h>
#include <math.h>
#include <stdint.h>

#define Nn 128
#define Tt 256
#define Dd 1024
#define Hh 1024
#define G4 4096
#define Pp 196
#define KR 2048   // recurrent K: [h | attn]
#define MX (Nn * Tt)

// ================= device scratch (static) =================
__device__ __align__(16) __nv_bfloat16 g_Wxh[(size_t)G4 * Dd];
__device__ __align__(16) __nv_bfloat16 g_Wxl[(size_t)G4 * Dd];
__device__ __align__(16) __nv_bfloat16 g_Wfh[(size_t)G4 * KR];
__device__ __align__(16) __nv_bfloat16 g_Wfl[(size_t)G4 * KR];
__device__ __align__(16) __nv_bfloat16 g_xh[(size_t)MX * Dd];
__device__ __align__(16) __nv_bfloat16 g_xl[(size_t)MX * Dd];
__device__ float g_xp[(size_t)MX * G4];
__device__ __align__(16) __nv_bfloat16 g_Abf[(size_t)Nn * Hh * Pp];  // bf16 A row-major
__device__ __align__(16) __nv_bfloat16 g_acth[(size_t)Nn * KR];
__device__ __align__(16) __nv_bfloat16 g_actl[(size_t)Nn * KR];
__device__ float g_bf[G4];
__device__ float g_hnewT[Hh * Nn];
__device__ float g_cT[Hh * Nn];
__device__ float g_sp[Nn][8][Pp];

// ================= helpers =================
__device__ __forceinline__ uint32_t smem_u32(const void* p) {
    uint32_t a;
    asm("{ .reg .u64 t; cvta.to.shared.u64 t, %1; cvt.u32.u64 %0, t; }" : "=r"(a) : "l"(p));
    return a;
}
__device__ __forceinline__ void cp16(uint32_t dst, const void* src) {
    asm volatile("cp.async.cg.shared.global [%0], [%1], 16;" :: "r"(dst), "l"(src));
}
__device__ __forceinline__ void cpcommit() { asm volatile("cp.async.commit_group;" ::: "memory"); }
template <int N> __device__ __forceinline__ void cpwait() {
    asm volatile("cp.async.wait_group %0;" :: "n"(N) : "memory");
}
__device__ __forceinline__ void barsync(int name) {
    asm volatile("bar.sync %0, 256;" :: "r"(name) : "memory");
}
__device__ __forceinline__ void ldsm_x4(uint32_t& r0, uint32_t& r1, uint32_t& r2, uint32_t& r3,
                                        uint32_t addr) {
    asm volatile("ldmatrix.sync.aligned.m8n8.x4.shared.b16 {%0,%1,%2,%3}, [%4];"
                 : "=r"(r0), "=r"(r1), "=r"(r2), "=r"(r3) : "r"(addr));
}
__device__ __forceinline__ void mma16816(float* d, const uint32_t* a, const uint32_t* b) {
    asm volatile(
        "mma.sync.aligned.m16n8k16.row.col.f32.bf16.bf16.f32 "
        "{%0,%1,%2,%3}, {%4,%5,%6,%7}, {%8,%9}, {%0,%1,%2,%3};"
        : "+f"(d[0]), "+f"(d[1]), "+f"(d[2]), "+f"(d[3])
        : "r"(a[0]), "r"(a[1]), "r"(a[2]), "r"(a[3]), "r"(b[0]), "r"(b[1]));
}
#define SWZ128(o) ((o) ^ (((o) >> 3) & 0x70))

__device__ __forceinline__ void bf16split(float v, __nv_bfloat16* hi, __nv_bfloat16* lo) {
    __nv_bfloat16 h = __float2bfloat16(v);
    *hi = h;
    *lo = __float2bfloat16(v - __bfloat162float(h));
}

// ================= one-time kernels =================
__global__ __launch_bounds__(256) void permute_kernel(
    const float* __restrict__ Wx, const float* __restrict__ Wh,
    const float* __restrict__ Wa, const float* __restrict__ b) {
    size_t total = (size_t)G4 * 3072;
    size_t stride = (size_t)gridDim.x * blockDim.x;
    for (size_t idx = (size_t)blockIdx.x * blockDim.x + threadIdx.x; idx < total; idx += stride) {
        int j = (int)(idx / 3072);
        int k = (int)(idx - (size_t)j * 3072);
        int src = (j & 3) * 1024 + (j >> 2);
        __nv_bfloat16 hi, lo;
        if (k < 1024) {
            bf16split(Wx[(size_t)k * G4 + src], &hi, &lo);
            g_Wxh[(size_t)j * Dd + k] = hi;
            g_Wxl[(size_t)j * Dd + k] = lo;
        } else {
            float v = (k < 2048) ? Wh[(size_t)(k - 1024) * G4 + src]
                                 : Wa[(size_t)(k - 2048) * G4 + src];
            bf16split(v, &hi, &lo);
            g_Wfh[(size_t)j * KR + (k - 1024)] = hi;
            g_Wfl[(size_t)j * KR + (k - 1024)] = lo;
        }
        if (k == 0) g_bf[j] = b[src];
    }
}

__global__ __launch_bounds__(256) void xsplit_kernel(const float* __restrict__ x) {
    size_t total = (size_t)MX * Dd;
    size_t stride = (size_t)gridDim.x * blockDim.x;
    for (size_t i = (size_t)blockIdx.x * blockDim.x + threadIdx.x; i < total; i += stride) {
        __nv_bfloat16 hi, lo;
        bf16split(x[i], &hi, &lo);
        g_xh[i] = hi;
        g_xl[i] = lo;
    }
}

__global__ __launch_bounds__(256) void a2bf_kernel(const float* __restrict__ A) {
    size_t total = (size_t)Nn * Hh * Pp;
    size_t stride = (size_t)gridDim.x * blockDim.x;
    for (size_t i = (size_t)blockIdx.x * blockDim.x + threadIdx.x; i < total; i += stride)
        g_Abf[i] = __float2bfloat16(A[i]);
}

__global__ __launch_bounds__(256) void init_kernel(const float* __restrict__ A) {
    int n = blockIdx.x;
    for (int u = threadIdx.x; u < Hh; u += blockDim.x) {
        const float4* r = (const float4*)(A + ((size_t)n * Hh + u) * Pp);
        float s = 0.f;
#pragma unroll
        for (int i = 0; i < 49; i++) {
            float4 v = r[i];
            s += v.x + v.y + v.z + v.w;
        }
        float m = s * (1.f / 196.f);
        g_hnewT[u * Nn + n] = m;
        g_cT[u * Nn + n] = m;
    }
}

// ================= shared mma pieces (KC=64, SW128) =================
#define KC 64
#define STB 40960
#define NSTG 3

__device__ __forceinline__ void load_chunk_g(
    int tid, int c, char* buf,
    const __nv_bfloat16* Ah, const __nv_bfloat16* Al, int lda,
    const __nv_bfloat16* Bh, const __nv_bfloat16* Bl, int ldb) {
    uint32_t sbase = smem_u32(buf);
#pragma unroll
    for (int it = 0; it < 4; it++) {
        int id = tid + it * 256;           // 0..1023 : 128 rows x 8 16B-chunks
        int m = id >> 3, kc = id & 7;
        uint32_t off = SWZ128((uint32_t)m * 128 + (uint32_t)kc * 16);
        size_t gidx = (size_t)m * lda + (size_t)c * KC + kc * 8;
        cp16(sbase + off, Ah + gidx);
        cp16(sbase + 16384 + off, Al + gidx);
    }
    {
        int nrow = tid >> 3, kc = tid & 7;  // 256 = 32 rows x 8 chunks
        uint32_t off = SWZ128((uint32_t)nrow * 128 + (uint32_t)kc * 16);
        size_t gidx = (size_t)nrow * ldb + (size_t)c * KC + kc * 8;
        cp16(sbase + 32768 + off, Bh + gidx);
        cp16(sbase + 36864 + off, Bl + gidx);
    }
    cpcommit();
}

// compute one KC=64 chunk from smem stage into acc (warp w of a 256-thread group)
__device__ __forceinline__ void compute_chunk(uint32_t sbase, int w, int lane, float acc[4][4]) {
    int arow = w * 16 + (lane & 15);
#pragma unroll
    for (int ks = 0; ks < 4; ks++) {
        int ak = ks * 16 + ((lane & 16) ? 8 : 0);
        uint32_t aoff = SWZ128((uint32_t)arow * 128 + (uint32_t)ak * 2);
        uint32_t ah[4], al[4];
        ldsm_x4(ah[0], ah[1], ah[2], ah[3], sbase + aoff);
        ldsm_x4(al[0], al[1], al[2], al[3], sbase + 16384 + aoff);
        uint32_t bh[8], bl[8];
        int bk = ks * 16 + ((lane & 8) ? 8 : 0);
#pragma unroll
        for (int jj = 0; jj < 2; jj++) {
            int nrow = jj * 16 + ((lane & 16) ? 8 : 0) + (lane & 7);
            uint32_t boff = SWZ128((uint32_t)nrow * 128 + (uint32_t)bk * 2);
            ldsm_x4(bh[4 * jj], bh[4 * jj + 1], bh[4 * jj + 2], bh[4 * jj + 3],
                    sbase + 32768 + boff);
            ldsm_x4(bl[4 * jj], bl[4 * jj + 1], bl[4 * jj + 2], bl[4 * jj + 3],
                    sbase + 36864 + boff);
        }
#pragma unroll
        for (int j = 0; j < 4; j++) {
            mma16816(acc[j], ah, &bh[2 * j]);
            mma16816(acc[j], ah, &bl[2 * j]);
            mma16816(acc[j], al, &bh[2 * j]);
        }
    }
}

// 256-thread 3-stage mainloop (used by xproj only)
__device__ __forceinline__ void mma_mainloop(
    int tid, char* dsm, float acc[4][4], int nch,
    const __nv_bfloat16* Ah, const __nv_bfloat16* Al, int lda,
    const __nv_bfloat16* Bh, const __nv_bfloat16* Bl, int ldb) {
    int w = tid >> 5, lane = tid & 31;
    load_chunk_g(tid, 0, dsm, Ah, Al, lda, Bh, Bl, ldb);
    load_chunk_g(tid, 1, dsm + STB, Ah, Al, lda, Bh, Bl, ldb);
    for (int c = 0; c < nch; c++) {
        if (c + 1 < nch) cpwait<1>(); else cpwait<0>();
        __syncthreads();
        compute_chunk(smem_u32(dsm + (c % NSTG) * STB), w, lane, acc);
        if (c + 2 < nch)
            load_chunk_g(tid, c + 2, dsm + ((c + 2) % NSTG) * STB, Ah, Al, lda, Bh, Bl, ldb);
    }
}

// ================= one-time: xproj = x @ Wx + b =================
__global__ __launch_bounds__(256) void xproj_kernel() {
    extern __shared__ __align__(1024) char dsm[];
    int tid = threadIdx.x;
    int w = tid >> 5, lane = tid & 31;
    int j0 = blockIdx.x * 32;
    int m0 = blockIdx.y * 128;

    float acc[4][4];
#pragma unroll
    for (int j = 0; j < 4; j++)
#pragma unroll
        for (int r = 0; r < 4; r++) acc[j][r] = 0.f;

    mma_mainloop(tid, dsm, acc, Dd / KC,
                 g_xh + (size_t)m0 * Dd, g_xl + (size_t)m0 * Dd, Dd,
                 g_Wxh + (size_t)j0 * Dd, g_Wxl + (size_t)j0 * Dd, Dd);

    int row0 = m0 + w * 16 + (lane >> 2);
#pragma unroll
    for (int j = 0; j < 4; j++) {
        int col = j0 + j * 8 + (lane & 3) * 2;
        float2 bb = *(const float2*)&g_bf[col];
        *(float2*)&g_xp[(size_t)row0 * G4 + col] = make_float2(acc[j][0] + bb.x, acc[j][1] + bb.y);
        *(float2*)&g_xp[(size_t)(row0 + 8) * G4 + col] = make_float2(acc[j][2] + bb.x, acc[j][3] + bb.y);
    }
}

// ================= scores partial: grid (8,128); bf16 A; commits h split (R11) ==========
__global__ __launch_bounds__(256) void scores_kernel(int t) {
    int uc = blockIdx.x;
    int n = (t & 1) ? (Nn - 1 - (int)blockIdx.y) : (int)blockIdx.y;  // zigzag by t
    int tid = threadIdx.x;
    int u0 = uc * 128;
    __shared__ float hsh[128];

    if (tid < 128) {
        float hv = g_hnewT[(u0 + tid) * Nn + n];
        __nv_bfloat16 hi, lo;
        bf16split(hv, &hi, &lo);
        g_acth[(size_t)n * KR + u0 + tid] = hi;
        g_actl[(size_t)n * KR + u0 + tid] = lo;
        hsh[tid] = hv;
    }
    __syncthreads();

    if (tid < Pp) {
        const __nv_bfloat16* ap = g_Abf + ((size_t)n * Hh + u0) * Pp + tid;
        float acc = 0.f;
#pragma unroll 8
        for (int u = 0; u < 128; u++) {
            acc += hsh[u] * __bfloat162float(ap[(size_t)u * Pp]);
        }
        g_sp[n][uc][tid] = acc;
    }
}

// ================= attn: softmax + weighted sum (bf16 A, R11) =================
__global__ __launch_bounds__(256) void attnsum_kernel(int t) {
    int uc = blockIdx.x;
    int n = (t & 1) ? (Nn - 1 - (int)blockIdx.y) : (int)blockIdx.y;  // zigzag by t
    int tid = threadIdx.x;
    __shared__ __align__(16) float w[Pp + 2];
    __shared__ float red[256];

    float myscore = 0.f, s = -3.4e38f;
    if (tid < Pp) {
        float acc = 0.f;
#pragma unroll
        for (int q = 0; q < 8; q++) acc += g_sp[n][q][tid];
        myscore = acc * 0.03125f;
        s = myscore;
    }
    red[tid] = s;
    __syncthreads();
    for (int off = 128; off > 0; off >>= 1) {
        if (tid < off) red[tid] = fmaxf(red[tid], red[tid + off]);
        __syncthreads();
    }
    float mx = red[0];
    __syncthreads();
    float e = (tid < Pp) ? expf(myscore - mx) : 0.f;
    red[tid] = e;
    __syncthreads();
    for (int off = 128; off > 0; off >>= 1) {
        if (tid < off) red[tid] += red[tid + off];
        __syncthreads();
    }
    float inv = 1.f / red[0];
    if (tid < Pp) w[tid] = e * inv;
    if (tid < 2) w[Pp + tid] = 0.f;
    __syncthreads();

    int u = uc * 256 + tid;
    const __nv_bfloat162* Ar = (const __nv_bfloat162*)(g_Abf + ((size_t)n * Hh + u) * Pp);
    float acc = 0.f;
#pragma unroll
    for (int i = 0; i < 98; i++) {
        float2 av = __bfloat1622float2(Ar[i]);
        acc += av.x * w[2 * i] + av.y * w[2 * i + 1];
    }
    __nv_bfloat16 hi, lo;
    bf16split(acc, &hi, &lo);
    g_acth[(size_t)n * KR + 1024 + u] = hi;
    g_actl[(size_t)n * KR + 1024 + u] = lo;
}

// ================= gates: 512 threads, 2 warp-groups on even/odd K-chunks ==============
// Group g (256 threads) processes chunks {g, g+2, ...} with its own 2-stage ring +
// named barrier. Accumulators merged via smem; group 0 runs the LSTM epilogue.
#define GCH 16   // chunks per group (KR/KC/2)
__global__ __launch_bounds__(512) void gates_mma_kernel(float* __restrict__ out, int t) {
    extern __shared__ __align__(1024) char dsm[];
    int tid = threadIdx.x;
    int g = tid >> 8;          // warp-group 0/1
    int gt = tid & 255;        // tid within group
    int w = gt >> 5, lane = tid & 31;
    int j0 = blockIdx.x * 32;

    const __nv_bfloat16* Bh = g_Wfh + (size_t)j0 * KR;
    const __nv_bfloat16* Bl = g_Wfl + (size_t)j0 * KR;

    float acc[4][4];
    if (g == 0) {
        int row0 = w * 16 + (lane >> 2);
#pragma unroll
        for (int j = 0; j < 4; j++) {
            int col = j0 + j * 8 + (lane & 3) * 2;
            float2 v0 = __ldcs((const float2*)&g_xp[((size_t)row0 * Tt + t) * G4 + col]);
            float2 v1 = __ldcs((const float2*)&g_xp[((size_t)(row0 + 8) * Tt + t) * G4 + col]);
            acc[j][0] = v0.x; acc[j][1] = v0.y; acc[j][2] = v1.x; acc[j][3] = v1.y;
        }
    } else {
#pragma unroll
        for (int j = 0; j < 4; j++)
#pragma unroll
            for (int r = 0; r < 4; r++) acc[j][r] = 0.f;
    }

    char* gbase = dsm + g * 2 * STB;
    int barname = 1 + g;

    // prologue: chunks g, g+2
    load_chunk_g(gt, g, gbase, g_acth, g_actl, KR, Bh, Bl, KR);
    load_chunk_g(gt, g + 2, gbase + STB, g_acth, g_actl, KR, Bh, Bl, KR);

    for (int i = 0; i < GCH; i++) {
        if (i + 1 < GCH) cpwait<1>(); else cpwait<0>();
        barsync(barname);
        compute_chunk(smem_u32(gbase + (i & 1) * STB), w, lane, acc);
        barsync(barname);   // all group warps done reading this stage
        if (i + 2 < GCH)
            load_chunk_g(gt, g + 2 * (i + 2), gbase + (i & 1) * STB,
                         g_acth, g_actl, KR, Bh, Bl, KR);
    }

    // merge accumulators: group 1 stages into its own (now idle) smem region
    float* stg = (float*)(dsm + 2 * STB);
    if (g == 1) {
#pragma unroll
        for (int j = 0; j < 4; j++)
#pragma unroll
            for (int r = 0; r < 4; r++) stg[gt * 16 + j * 4 + r] = acc[j][r];
    }
    __syncthreads();
    if (g != 0) return;

#pragma unroll
    for (int j = 0; j < 4; j++)
#pragma unroll
        for (int r = 0; r < 4; r++) acc[j][r] += stg[gt * 16 + j * 4 + r];

    // ---- fused LSTM epilogue (group 0, identical mapping to before) ----
    int q = lane & 3;
    int rbase = w * 16 + (lane >> 2);
#pragma unroll
    for (int j = 0; j < 4; j++) {
        float e0 = __shfl_xor_sync(0xffffffff, acc[j][0], 1);
        float e1 = __shfl_xor_sync(0xffffffff, acc[j][1], 1);
        float e2 = __shfl_xor_sync(0xffffffff, acc[j][2], 1);
        float e3 = __shfl_xor_sync(0xffffffff, acc[j][3], 1);
        int u = blockIdx.x * 8 + 2 * j + (q >> 1);
        int m;
        float ai, af, ao, ag;
        if ((q & 1) == 0) {
            m = rbase;
            ai = acc[j][0]; af = acc[j][1]; ao = e0; ag = e1;
        } else {
            m = rbase + 8;
            ai = e2; af = e3; ao = acc[j][2]; ag = acc[j][3];
        }
        float ig = 1.f / (1.f + expf(-ai));
        float fg = 1.f / (1.f + expf(-af));
        float og = 1.f / (1.f + expf(-ao));
        float gg = tanhf(ag);
        float cn = fg * g_cT[u * Nn + m] + ig * gg;
        float hn = og * tanhf(cn);
        g_cT[u * Nn + m] = cn;
        g_hnewT[u * Nn + m] = hn;
        __stcs(&out[((size_t)m * Tt + t) * Hh + u], hn);
    }
}

extern "C" void kernel_launch(void* const* d_in, const int* in_sizes, int n_in,
                              void* d_out, int out_size) {
    const float* x  = (const float*)d_in[0];
    const float* A  = (const float*)d_in[1];
    const float* Wx = (const float*)d_in[2];
    const float* Wh = (const float*)d_in[3];
    const float* Wa = (const float*)d_in[4];
    const float* b  = (const float*)d_in[5];
    float* out = (float*)d_out;

    cudaFuncSetAttribute(gates_mma_kernel, cudaFuncAttributeMaxDynamicSharedMemorySize, 4 * STB);
    cudaFuncSetAttribute(xproj_kernel, cudaFuncAttributeMaxDynamicSharedMemorySize, NSTG * STB);

    permute_kernel<<<2048, 256>>>(Wx, Wh, Wa, b);
    xsplit_kernel<<<4096, 256>>>(x);
    a2bf_kernel<<<4096, 256>>>(A);
    init_kernel<<<Nn, 256>>>(A);
    xproj_kernel<<<dim3(G4 / 32, MX / 128), 256, NSTG * STB>>>();
    for (int t = 0; t < Tt; t++) {
        scores_kernel<<<dim3(8, Nn), 256>>>(t);
        attnsum_kernel<<<dim3(4, Nn), 256>>>(t);
        gates_mma_kernel<<<G4 / 32, 512, 4 * STB>>>(out, t);
    }
}

// round 17
// speedup vs baseline: 1.6006x; 1.3106x over previous
#include <cuda_runtime.h>
#include <cuda_fp16.h>
#include <math.h>
#include <stdint.h>

#define Nn 128
#define Tt 256
#define Dd 1024
#define Hh 1024
#define G4 4096
#define Pp 196
#define KR 2048   // recurrent K: [h | attn]
#define MX (Nn * Tt)

// ================= device scratch (static) =================
__device__ __align__(16) __half g_Wxh[(size_t)G4 * Dd];   // Wx^T fp16 (hi only)
__device__ __align__(16) __half g_Wfh[(size_t)G4 * KR];   // [Wh;Wattn]^T fp16 (hi only)
__device__ __align__(16) __half g_xh[(size_t)MX * Dd];    // x split hi
__device__ __align__(16) __half g_xl[(size_t)MX * Dd];    // x split lo
__device__ float g_xp[(size_t)MX * G4];
__device__ __align__(16) __half g_Ah[(size_t)Nn * Hh * Pp];  // fp16 A row-major
__device__ __align__(16) __half g_acth[(size_t)Nn * KR];
__device__ __align__(16) __half g_actl[(size_t)Nn * KR];
__device__ float g_bf[G4];
__device__ float g_hnewT[Hh * Nn];
__device__ float g_cT[Hh * Nn];
__device__ float g_sp[Nn][8][Pp];

// ================= helpers =================
__device__ __forceinline__ uint32_t smem_u32(const void* p) {
    uint32_t a;
    asm("{ .reg .u64 t; cvta.to.shared.u64 t, %1; cvt.u32.u64 %0, t; }" : "=r"(a) : "l"(p));
    return a;
}
__device__ __forceinline__ void cp16(uint32_t dst, const void* src) {
    asm volatile("cp.async.cg.shared.global [%0], [%1], 16;" :: "r"(dst), "l"(src));
}
__device__ __forceinline__ void cpcommit() { asm volatile("cp.async.commit_group;" ::: "memory"); }
template <int N> __device__ __forceinline__ void cpwait() {
    asm volatile("cp.async.wait_group %0;" :: "n"(N) : "memory");
}
__device__ __forceinline__ void barsync(int name) {
    asm volatile("bar.sync %0, 256;" :: "r"(name) : "memory");
}
__device__ __forceinline__ void ldsm_x4(uint32_t& r0, uint32_t& r1, uint32_t& r2, uint32_t& r3,
                                        uint32_t addr) {
    asm volatile("ldmatrix.sync.aligned.m8n8.x4.shared.b16 {%0,%1,%2,%3}, [%4];"
                 : "=r"(r0), "=r"(r1), "=r"(r2), "=r"(r3) : "r"(addr));
}
__device__ __forceinline__ void mma16816(float* d, const uint32_t* a, const uint32_t* b) {
    asm volatile(
        "mma.sync.aligned.m16n8k16.row.col.f32.f16.f16.f32 "
        "{%0,%1,%2,%3}, {%4,%5,%6,%7}, {%8,%9}, {%0,%1,%2,%3};"
        : "+f"(d[0]), "+f"(d[1]), "+f"(d[2]), "+f"(d[3])
        : "r"(a[0]), "r"(a[1]), "r"(a[2]), "r"(a[3]), "r"(b[0]), "r"(b[1]));
}
#define SWZ128(o) ((o) ^ (((o) >> 3) & 0x70))

__device__ __forceinline__ void f16split(float v, __half* hi, __half* lo) {
    __half h = __float2half(v);
    *hi = h;
    *lo = __float2half(v - __half2float(h));
}

// ================= one-time kernels =================
__global__ __launch_bounds__(256) void permute_kernel(
    const float* __restrict__ Wx, const float* __restrict__ Wh,
    const float* __restrict__ Wa, const float* __restrict__ b) {
    size_t total = (size_t)G4 * 3072;
    size_t stride = (size_t)gridDim.x * blockDim.x;
    for (size_t idx = (size_t)blockIdx.x * blockDim.x + threadIdx.x; idx < total; idx += stride) {
        int j = (int)(idx / 3072);
        int k = (int)(idx - (size_t)j * 3072);
        int src = (j & 3) * 1024 + (j >> 2);
        if (k < 1024) {
            g_Wxh[(size_t)j * Dd + k] = __float2half(Wx[(size_t)k * G4 + src]);
        } else {
            float v = (k < 2048) ? Wh[(size_t)(k - 1024) * G4 + src]
                                 : Wa[(size_t)(k - 2048) * G4 + src];
            g_Wfh[(size_t)j * KR + (k - 1024)] = __float2half(v);
        }
        if (k == 0) g_bf[j] = b[src];
    }
}

__global__ __launch_bounds__(256) void xsplit_kernel(const float* __restrict__ x) {
    size_t total = (size_t)MX * Dd;
    size_t stride = (size_t)gridDim.x * blockDim.x;
    for (size_t i = (size_t)blockIdx.x * blockDim.x + threadIdx.x; i < total; i += stride) {
        __half hi, lo;
        f16split(x[i], &hi, &lo);
        g_xh[i] = hi;
        g_xl[i] = lo;
    }
}

__global__ __launch_bounds__(256) void a2h_kernel(const float* __restrict__ A) {
    size_t total = (size_t)Nn * Hh * Pp;
    size_t stride = (size_t)gridDim.x * blockDim.x;
    for (size_t i = (size_t)blockIdx.x * blockDim.x + threadIdx.x; i < total; i += stride)
        g_Ah[i] = __float2half(A[i]);
}

__global__ __launch_bounds__(256) void init_kernel(const float* __restrict__ A) {
    int n = blockIdx.x;
    for (int u = threadIdx.x; u < Hh; u += blockDim.x) {
        const float4* r = (const float4*)(A + ((size_t)n * Hh + u) * Pp);
        float s = 0.f;
#pragma unroll
        for (int i = 0; i < 49; i++) {
            float4 v = r[i];
            s += v.x + v.y + v.z + v.w;
        }
        float m = s * (1.f / 196.f);
        g_hnewT[u * Nn + n] = m;
        g_cT[u * Nn + n] = m;
    }
}

// ================= shared mma pieces (KC=64, SW128, fp16 2-term) =================
#define KC 64
#define STB 36864
#define NSTG 3

__device__ __forceinline__ void load_chunk_g(
    int tid, int c, char* buf,
    const __half* Ah, const __half* Al, int lda,
    const __half* Bh, int ldb) {
    uint32_t sbase = smem_u32(buf);
#pragma unroll
    for (int it = 0; it < 4; it++) {
        int id = tid + it * 256;           // 0..1023 : 128 rows x 8 16B-chunks
        int m = id >> 3, kc = id & 7;
        uint32_t off = SWZ128((uint32_t)m * 128 + (uint32_t)kc * 16);
        size_t gidx = (size_t)m * lda + (size_t)c * KC + kc * 8;
        cp16(sbase + off, Ah + gidx);
        cp16(sbase + 16384 + off, Al + gidx);
    }
    {
        int nrow = tid >> 3, kc = tid & 7;  // 256 = 32 rows x 8 chunks
        uint32_t off = SWZ128((uint32_t)nrow * 128 + (uint32_t)kc * 16);
        size_t gidx = (size_t)nrow * ldb + (size_t)c * KC + kc * 8;
        cp16(sbase + 32768 + off, Bh + gidx);
    }
    cpcommit();
}

// compute one KC=64 chunk: D += Ah*Bh + Al*Bh
__device__ __forceinline__ void compute_chunk(uint32_t sbase, int w, int lane, float acc[4][4]) {
    int arow = w * 16 + (lane & 15);
#pragma unroll
    for (int ks = 0; ks < 4; ks++) {
        int ak = ks * 16 + ((lane & 16) ? 8 : 0);
        uint32_t aoff = SWZ128((uint32_t)arow * 128 + (uint32_t)ak * 2);
        uint32_t ah[4], al[4];
        ldsm_x4(ah[0], ah[1], ah[2], ah[3], sbase + aoff);
        ldsm_x4(al[0], al[1], al[2], al[3], sbase + 16384 + aoff);
        uint32_t bh[8];
        int bk = ks * 16 + ((lane & 8) ? 8 : 0);
#pragma unroll
        for (int jj = 0; jj < 2; jj++) {
            int nrow = jj * 16 + ((lane & 16) ? 8 : 0) + (lane & 7);
            uint32_t boff = SWZ128((uint32_t)nrow * 128 + (uint32_t)bk * 2);
            ldsm_x4(bh[4 * jj], bh[4 * jj + 1], bh[4 * jj + 2], bh[4 * jj + 3],
                    sbase + 32768 + boff);
        }
#pragma unroll
        for (int j = 0; j < 4; j++) {
            mma16816(acc[j], ah, &bh[2 * j]);
            mma16816(acc[j], al, &bh[2 * j]);
        }
    }
}

// 256-thread 3-stage mainloop (xproj)
__device__ __forceinline__ void mma_mainloop(
    int tid, char* dsm, float acc[4][4], int nch,
    const __half* Ah, const __half* Al, int lda,
    const __half* Bh, int ldb) {
    int w = tid >> 5, lane = tid & 31;
    load_chunk_g(tid, 0, dsm, Ah, Al, lda, Bh, ldb);
    load_chunk_g(tid, 1, dsm + STB, Ah, Al, lda, Bh, ldb);
    for (int c = 0; c < nch; c++) {
        if (c + 1 < nch) cpwait<1>(); else cpwait<0>();
        __syncthreads();
        compute_chunk(smem_u32(dsm + (c % NSTG) * STB), w, lane, acc);
        if (c + 2 < nch)
            load_chunk_g(tid, c + 2, dsm + ((c + 2) % NSTG) * STB, Ah, Al, lda, Bh, ldb);
    }
}

// ================= one-time: xproj = x @ Wx + b =================
__global__ __launch_bounds__(256) void xproj_kernel() {
    extern __shared__ __align__(1024) char dsm[];
    int tid = threadIdx.x;
    int w = tid >> 5, lane = tid & 31;
    int j0 = blockIdx.x * 32;
    int m0 = blockIdx.y * 128;

    float acc[4][4];
#pragma unroll
    for (int j = 0; j < 4; j++)
#pragma unroll
        for (int r = 0; r < 4; r++) acc[j][r] = 0.f;

    mma_mainloop(tid, dsm, acc, Dd / KC,
                 g_xh + (size_t)m0 * Dd, g_xl + (size_t)m0 * Dd, Dd,
                 g_Wxh + (size_t)j0 * Dd, Dd);

    int row0 = m0 + w * 16 + (lane >> 2);
#pragma unroll
    for (int j = 0; j < 4; j++) {
        int col = j0 + j * 8 + (lane & 3) * 2;
        float2 bb = *(const float2*)&g_bf[col];
        *(float2*)&g_xp[(size_t)row0 * G4 + col] = make_float2(acc[j][0] + bb.x, acc[j][1] + bb.y);
        *(float2*)&g_xp[(size_t)(row0 + 8) * G4 + col] = make_float2(acc[j][2] + bb.x, acc[j][3] + bb.y);
    }
}

// ================= scores partial: grid (8,128); fp16 A; commits h split ==========
__global__ __launch_bounds__(256) void scores_kernel(int t) {
    int uc = blockIdx.x;
    int n = (t & 1) ? (Nn - 1 - (int)blockIdx.y) : (int)blockIdx.y;  // zigzag by t
    int tid = threadIdx.x;
    int u0 = uc * 128;
    __shared__ float hsh[128];

    if (tid < 128) {
        float hv = g_hnewT[(u0 + tid) * Nn + n];
        __half hi, lo;
        f16split(hv, &hi, &lo);
        g_acth[(size_t)n * KR + u0 + tid] = hi;
        g_actl[(size_t)n * KR + u0 + tid] = lo;
        hsh[tid] = hv;
    }
    __syncthreads();

    if (tid < Pp) {
        const __half* ap = g_Ah + ((size_t)n * Hh + u0) * Pp + tid;
        float acc = 0.f;
#pragma unroll 8
        for (int u = 0; u < 128; u++) {
            acc += hsh[u] * __half2float(ap[(size_t)u * Pp]);
        }
        g_sp[n][uc][tid] = acc;
    }
}

// ================= attn: softmax + weighted sum (fp16 A) =================
__global__ __launch_bounds__(256) void attnsum_kernel(int t) {
    int uc = blockIdx.x;
    int n = (t & 1) ? (Nn - 1 - (int)blockIdx.y) : (int)blockIdx.y;  // zigzag by t
    int tid = threadIdx.x;
    __shared__ __align__(16) float w[Pp + 2];
    __shared__ float red[256];

    float myscore = 0.f, s = -3.4e38f;
    if (tid < Pp) {
        float acc = 0.f;
#pragma unroll
        for (int q = 0; q < 8; q++) acc += g_sp[n][q][tid];
        myscore = acc * 0.03125f;
        s = myscore;
    }
    red[tid] = s;
    __syncthreads();
    for (int off = 128; off > 0; off >>= 1) {
        if (tid < off) red[tid] = fmaxf(red[tid], red[tid + off]);
        __syncthreads();
    }
    float mx = red[0];
    __syncthreads();
    float e = (tid < Pp) ? expf(myscore - mx) : 0.f;
    red[tid] = e;
    __syncthreads();
    for (int off = 128; off > 0; off >>= 1) {
        if (tid < off) red[tid] += red[tid + off];
        __syncthreads();
    }
    float inv = 1.f / red[0];
    if (tid < Pp) w[tid] = e * inv;
    if (tid < 2) w[Pp + tid] = 0.f;
    __syncthreads();

    int u = uc * 256 + tid;
    const __half2* Ar = (const __half2*)(g_Ah + ((size_t)n * Hh + u) * Pp);
    float acc = 0.f;
#pragma unroll
    for (int i = 0; i < 98; i++) {
        float2 av = __half22float2(Ar[i]);
        acc += av.x * w[2 * i] + av.y * w[2 * i + 1];
    }
    __half hi, lo;
    f16split(acc, &hi, &lo);
    g_acth[(size_t)n * KR + 1024 + u] = hi;
    g_actl[(size_t)n * KR + 1024 + u] = lo;
}

// ================= gates: 512 threads, 2 warp-groups on even/odd K-chunks ==============
#define GCH 16   // chunks per group (KR/KC/2)
__global__ __launch_bounds__(512) void gates_mma_kernel(float* __restrict__ out, int t) {
    extern __shared__ __align__(1024) char dsm[];
    int tid = threadIdx.x;
    int g = tid >> 8;          // warp-group 0/1
    int gt = tid & 255;        // tid within group
    int w = gt >> 5, lane = tid & 31;
    int j0 = blockIdx.x * 32;

    const __half* Bh = g_Wfh + (size_t)j0 * KR;

    float acc[4][4];
    if (g == 0) {
        int row0 = w * 16 + (lane >> 2);
#pragma unroll
        for (int j = 0; j < 4; j++) {
            int col = j0 + j * 8 + (lane & 3) * 2;
            float2 v0 = __ldcs((const float2*)&g_xp[((size_t)row0 * Tt + t) * G4 + col]);
            float2 v1 = __ldcs((const float2*)&g_xp[((size_t)(row0 + 8) * Tt + t) * G4 + col]);
            acc[j][0] = v0.x; acc[j][1] = v0.y; acc[j][2] = v1.x; acc[j][3] = v1.y;
        }
    } else {
#pragma unroll
        for (int j = 0; j < 4; j++)
#pragma unroll
            for (int r = 0; r < 4; r++) acc[j][r] = 0.f;
    }

    char* gbase = dsm + g * 2 * STB;
    int barname = 1 + g;

    load_chunk_g(gt, g, gbase, g_acth, g_actl, KR, Bh, KR);
    load_chunk_g(gt, g + 2, gbase + STB, g_acth, g_actl, KR, Bh, KR);

    for (int i = 0; i < GCH; i++) {
        if (i + 1 < GCH) cpwait<1>(); else cpwait<0>();
        barsync(barname);
        compute_chunk(smem_u32(gbase + (i & 1) * STB), w, lane, acc);
        barsync(barname);
        if (i + 2 < GCH)
            load_chunk_g(gt, g + 2 * (i + 2), gbase + (i & 1) * STB,
                         g_acth, g_actl, KR, Bh, KR);
    }

    float* stg = (float*)(dsm + 2 * STB);
    if (g == 1) {
#pragma unroll
        for (int j = 0; j < 4; j++)
#pragma unroll
            for (int r = 0; r < 4; r++) stg[gt * 16 + j * 4 + r] = acc[j][r];
    }
    __syncthreads();
    if (g != 0) return;

#pragma unroll
    for (int j = 0; j < 4; j++)
#pragma unroll
        for (int r = 0; r < 4; r++) acc[j][r] += stg[gt * 16 + j * 4 + r];

    int q = lane & 3;
    int rbase = w * 16 + (lane >> 2);
#pragma unroll
    for (int j = 0; j < 4; j++) {
        float e0 = __shfl_xor_sync(0xffffffff, acc[j][0], 1);
        float e1 = __shfl_xor_sync(0xffffffff, acc[j][1], 1);
        float e2 = __shfl_xor_sync(0xffffffff, acc[j][2], 1);
        float e3 = __shfl_xor_sync(0xffffffff, acc[j][3], 1);
        int u = blockIdx.x * 8 + 2 * j + (q >> 1);
        int m;
        float ai, af, ao, ag;
        if ((q & 1) == 0) {
            m = rbase;
            ai = acc[j][0]; af = acc[j][1]; ao = e0; ag = e1;
        } else {
            m = rbase + 8;
            ai = e2; af = e3; ao = acc[j][2]; ag = acc[j][3];
        }
        float ig = 1.f / (1.f + expf(-ai));
        float fg = 1.f / (1.f + expf(-af));
        float og = 1.f / (1.f + expf(-ao));
        float gg = tanhf(ag);
        float cn = fg * g_cT[u * Nn + m] + ig * gg;
        float hn = og * tanhf(cn);
        g_cT[u * Nn + m] = cn;
        g_hnewT[u * Nn + m] = hn;
        __stcs(&out[((size_t)m * Tt + t) * Hh + u], hn);
    }
}

extern "C" void kernel_launch(void* const* d_in, const int* in_sizes, int n_in,
                              void* d_out, int out_size) {
    const float* x  = (const float*)d_in[0];
    const float* A  = (const float*)d_in[1];
    const float* Wx = (const float*)d_in[2];
    const float* Wh = (const float*)d_in[3];
    const float* Wa = (const float*)d_in[4];
    const float* b  = (const float*)d_in[5];
    float* out = (float*)d_out;

    cudaFuncSetAttribute(gates_mma_kernel, cudaFuncAttributeMaxDynamicSharedMemorySize, 4 * STB);
    cudaFuncSetAttribute(xproj_kernel, cudaFuncAttributeMaxDynamicSharedMemorySize, NSTG * STB);

    permute_kernel<<<2048, 256>>>(Wx, Wh, Wa, b);
    xsplit_kernel<<<4096, 256>>>(x);
    a2h_kernel<<<4096, 256>>>(A);
    init_kernel<<<Nn, 256>>>(A);
    xproj_kernel<<<dim3(G4 / 32, MX / 128), 256, NSTG * STB>>>();
    for (int t = 0; t < Tt; t++) {
        scores_kernel<<<dim3(8, Nn), 256>>>(t);
        attnsum_kernel<<<dim3(4, Nn), 256>>>(t);
        gates_mma_kernel<<<G4 / 32, 512, 4 * STB>>>(out, t);
    }
}